// round 1
// baseline (speedup 1.0000x reference)
#include <cuda_runtime.h>
#include <cstdint>

#define T_STEPS 2048
#define BATCH 16
#define DIM 1024
#define NCTA 128
#define STEP_ELEMS (BATCH * DIM)                 // 16384
#define OUTS_ELEMS ((size_t)T_STEPS * STEP_ELEMS) // 33554432

// Monotonic grid-barrier counter. Reset by init_kernel every launch/replay.
__device__ unsigned int g_count;

__device__ __forceinline__ float my_tanh(float x) {
    float ax = fabsf(x);
    float e  = __expf(2.0f * ax);
    float r  = 1.0f - 2.0f / (e + 1.0f);
    return copysignf(r, x);
}
__device__ __forceinline__ float my_sigmoid(float x) {
    return 1.0f / (1.0f + __expf(-x));
}

// ---------------------------------------------------------------------------
// Init: copy h0 into h-output slot 0, reset the grid barrier counter.
// ---------------------------------------------------------------------------
__global__ void init_kernel(const float* __restrict__ h0, float* __restrict__ hbuf) {
    int i = blockIdx.x * blockDim.x + threadIdx.x;
    if (i < STEP_ELEMS) hbuf[i] = h0[i];
    if (i == 0) g_count = 0u;
}

// ---------------------------------------------------------------------------
// GEMM: C[m,n] = sum_k A[m,k] * B[n,k] + bias[n]
// M = 32768 (t*16+b), N = 1024 (e), K = 1024 (d). Both operands K-contiguous.
// 128x128 tile, BK=8, 256 threads, 8x8 micro-tile, single-stage reg prefetch.
// ---------------------------------------------------------------------------
__global__ void __launch_bounds__(256, 2)
gemm_kernel(const float* __restrict__ A, const float* __restrict__ Bw,
            const float* __restrict__ bias, float* __restrict__ C) {
    __shared__ float As[8][128];
    __shared__ float Bs[8][128];

    const int tid = threadIdx.x;
    const int m0 = blockIdx.x * 128;
    const int n0 = blockIdx.y * 128;
    const int lr = tid >> 1;          // 0..127
    const int lc = (tid & 1) * 4;     // 0 or 4
    const int tx = tid & 15;
    const int ty = tid >> 4;

    const float* Ab = A  + (size_t)(m0 + lr) * DIM + lc;
    const float* Bb = Bw + (size_t)(n0 + lr) * DIM + lc;

    float acc[8][8];
#pragma unroll
    for (int i = 0; i < 8; i++)
#pragma unroll
        for (int j = 0; j < 8; j++) acc[i][j] = 0.0f;

    float4 a4 = *(const float4*)Ab;
    float4 b4 = *(const float4*)Bb;

#pragma unroll 1
    for (int kt = 0; kt < 128; kt++) {
        As[lc + 0][lr] = a4.x; As[lc + 1][lr] = a4.y;
        As[lc + 2][lr] = a4.z; As[lc + 3][lr] = a4.w;
        Bs[lc + 0][lr] = b4.x; Bs[lc + 1][lr] = b4.y;
        Bs[lc + 2][lr] = b4.z; Bs[lc + 3][lr] = b4.w;
        __syncthreads();

        if (kt < 127) {
            a4 = *(const float4*)(Ab + (kt + 1) * 8);
            b4 = *(const float4*)(Bb + (kt + 1) * 8);
        }

#pragma unroll
        for (int kk = 0; kk < 8; kk++) {
            float af[8], bf[8];
            *(float4*)&af[0] = *(const float4*)&As[kk][ty * 8];
            *(float4*)&af[4] = *(const float4*)&As[kk][ty * 8 + 4];
            *(float4*)&bf[0] = *(const float4*)&Bs[kk][tx * 8];
            *(float4*)&bf[4] = *(const float4*)&Bs[kk][tx * 8 + 4];
#pragma unroll
            for (int i = 0; i < 8; i++)
#pragma unroll
                for (int j = 0; j < 8; j++)
                    acc[i][j] = fmaf(af[i], bf[j], acc[i][j]);
        }
        __syncthreads();
    }

#pragma unroll
    for (int i = 0; i < 8; i++) {
        size_t row = (size_t)(m0 + ty * 8 + i) * DIM + n0 + tx * 8;
#pragma unroll
        for (int j = 0; j < 8; j++)
            C[row + j] = acc[i][j] + bias[n0 + tx * 8 + j];
    }
}

// ---------------------------------------------------------------------------
// Persistent recurrence kernel. 128 CTAs x 256 threads.
// CTA c owns output columns e = c*8 .. c*8+7.
// Thread layout: e_loc = tid & 7, chunk = tid >> 3 (32 k-chunks of 32 each).
// Each thread holds W_h[e, chunk*32 .. +31] in registers (permuted by `rot`
// so that the 4 chunk-groups within a warp read distinct smem banks).
// ---------------------------------------------------------------------------
__global__ void __launch_bounds__(256, 1)
rnn_kernel(const float* __restrict__ Wh, const float* __restrict__ la,
           float* __restrict__ outs, float* __restrict__ hbuf) {
    extern __shared__ float sm[];
    float* h_sh = sm;            // 16384 floats (64 KB)
    float* part = sm + 16384;    // 4096 floats  (16 KB)

    const int tid   = threadIdx.x;
    const int e_loc = tid & 7;
    const int chunk = tid >> 3;        // 0..31
    const int k0    = chunk * 32;
    const int e     = blockIdx.x * 8 + e_loc;
    const int rot   = chunk & 7;

    const float alpha = __expf(la[0]);

    // Persistent W_h slice, permuted: w4[jj] pairs with h-offset joff[jj].
    float4 w4[8];
    int joff[8];
    {
        const float4* wp = reinterpret_cast<const float4*>(Wh + (size_t)e * DIM + k0);
#pragma unroll
        for (int jj = 0; jj < 8; jj++) {
            int j = (jj + rot) & 7;
            w4[jj]   = wp[j];
            joff[jj] = 4 * j;
        }
    }

    const int fb = tid >> 3;   // finalize: batch row (tid < 128)
    const int fe = tid & 7;    // finalize: local e column
    const int eg = blockIdx.x * 8 + fe;

    for (int t = 0; t < T_STEPS; t++) {
        const size_t obase = (size_t)t * STEP_ELEMS;

        // Prefetch wx early (latency hidden under the GEMM below).
        float wx = 0.0f;
        if (tid < 128) wx = outs[obase + (size_t)fb * DIM + eg];

        // Cooperative load of h[t] into smem (L1-bypass: written by peers).
        {
            const float4* hs4 = reinterpret_cast<const float4*>(hbuf + obase);
            float4* hh4 = reinterpret_cast<float4*>(h_sh);
#pragma unroll
            for (int i = 0; i < 16; i++)
                hh4[tid + 256 * i] = __ldcg(&hs4[tid + 256 * i]);
        }
        __syncthreads();

        // Partial dot products: acc[b] = sum over this thread's 32 k's.
        float acc[16];
#pragma unroll
        for (int b = 0; b < 16; b++) acc[b] = 0.0f;
#pragma unroll
        for (int jj = 0; jj < 8; jj++) {
            const float4 w = w4[jj];
            const int off = k0 + joff[jj];
#pragma unroll
            for (int b = 0; b < 16; b++) {
                float4 h4 = *(const float4*)(h_sh + b * DIM + off);
                float a = acc[b];
                a = fmaf(h4.x, w.x, a);
                a = fmaf(h4.y, w.y, a);
                a = fmaf(h4.z, w.z, a);
                a = fmaf(h4.w, w.w, a);
                acc[b] = a;
            }
        }

#pragma unroll
        for (int b = 0; b < 16; b++)
            part[(chunk * 16 + b) * 8 + e_loc] = acc[b];
        __syncthreads();

        if (tid < 128) {
            float s0 = 0.f, s1 = 0.f, s2 = 0.f, s3 = 0.f;
#pragma unroll
            for (int c = 0; c < 32; c += 4) {
                s0 += part[((c + 0) * 16 + fb) * 8 + fe];
                s1 += part[((c + 1) * 16 + fb) * 8 + fe];
                s2 += part[((c + 2) * 16 + fb) * 8 + fe];
                s3 += part[((c + 3) * 16 + fb) * 8 + fe];
            }
            float pre  = (s0 + s1) + (s2 + s3) + wx;
            float hold = h_sh[fb * DIM + eg];
            float hn   = hold + alpha * my_tanh(pre);
            float ot   = hn * hn * my_sigmoid(hn);
            __stcg(&hbuf[(size_t)(t + 1) * STEP_ELEMS + (size_t)fb * DIM + eg], hn);
            outs[obase + (size_t)fb * DIM + eg] = ot;
        }

        // Grid barrier: monotonic counter, target = NCTA*(t+1).
        __threadfence();
        __syncthreads();
        if (tid == 0) {
            unsigned tgt = (unsigned)(t + 1) * NCTA;
            unsigned a = atomicAdd(&g_count, 1u) + 1u;
            if (a != tgt) {
                volatile unsigned* p = &g_count;
                while (*p < tgt) { }
            }
            __threadfence();
        }
        __syncthreads();
    }
}

// ---------------------------------------------------------------------------
// kernel_launch
//   inputs: x[T,B,D], h0[B,D], W_x[D,D], W_h[D,D], b[D], log_alpha[1]
//   output: [ outs (T*B*D) | h ((T+1)*B*D) ]  float32
//   The outs region doubles as the Wx_all scratch: gemm writes Wx there,
//   rnn reads wx[t,b,e] and overwrites the same element with out[t,b,e].
// ---------------------------------------------------------------------------
extern "C" void kernel_launch(void* const* d_in, const int* in_sizes, int n_in,
                              void* d_out, int out_size) {
    const float* x    = (const float*)d_in[0];
    const float* h0   = (const float*)d_in[1];
    const float* Wx   = (const float*)d_in[2];
    const float* Wh   = (const float*)d_in[3];
    const float* bias = (const float*)d_in[4];
    const float* la   = (const float*)d_in[5];

    float* outs = (float*)d_out;
    float* hbuf = outs + OUTS_ELEMS;

    cudaFuncSetAttribute(rnn_kernel, cudaFuncAttributeMaxDynamicSharedMemorySize,
                         (16384 + 4096) * sizeof(float));

    init_kernel<<<32, 512>>>(h0, hbuf);

    dim3 gg(32768 / 128, DIM / 128);
    gemm_kernel<<<gg, 256>>>(x, Wx, bias, outs);

    rnn_kernel<<<NCTA, 256, (16384 + 4096) * sizeof(float)>>>(Wh, la, outs, hbuf);
}

// round 4
// speedup vs baseline: 1.1886x; 1.1886x over previous
#include <cuda_runtime.h>
#include <cstdint>

#define T_STEPS 2048
#define BATCH 16
#define DIM 1024
#define NCTA 128
#define STEP_ELEMS (BATCH * DIM)                  // 16384
#define OUTS_ELEMS ((size_t)T_STEPS * STEP_ELEMS) // 33554432

// Monotonic grid-barrier counter. Reset by init_kernel every launch/replay.
__device__ unsigned int g_count;

__device__ __forceinline__ float my_tanh(float x) {
    float ax = fabsf(x);
    float e  = __expf(2.0f * ax);
    float r  = 1.0f - 2.0f / (e + 1.0f);
    return copysignf(r, x);
}
__device__ __forceinline__ float my_sigmoid(float x) {
    return 1.0f / (1.0f + __expf(-x));
}

__device__ __forceinline__ void cp_async16(uint32_t smem_addr, const void* gptr) {
    asm volatile("cp.async.cg.shared.global [%0], [%1], 16;\n"
                 :: "r"(smem_addr), "l"(gptr) : "memory");
}
__device__ __forceinline__ void cp_commit() {
    asm volatile("cp.async.commit_group;\n" ::: "memory");
}
#define CP_WAIT(n) asm volatile("cp.async.wait_group %0;\n" :: "n"(n) : "memory")

__device__ __forceinline__ void bar_arrive_release() {
    unsigned* p = &g_count;
    asm volatile("red.add.release.gpu.u32 [%0], %1;" :: "l"(p), "r"(1u) : "memory");
}
__device__ __forceinline__ unsigned bar_ld_acquire() {
    unsigned v;
    unsigned* p = &g_count;
    asm volatile("ld.acquire.gpu.u32 %0, [%1];" : "=r"(v) : "l"(p) : "memory");
    return v;
}

// ---------------------------------------------------------------------------
// Init: copy h0 into h-output slot 0, reset the grid barrier counter.
// ---------------------------------------------------------------------------
__global__ void init_kernel(const float* __restrict__ h0, float* __restrict__ hbuf) {
    int i = blockIdx.x * blockDim.x + threadIdx.x;
    if (i < STEP_ELEMS) hbuf[i] = h0[i];
    if (i == 0) g_count = 0u;
}

// ---------------------------------------------------------------------------
// GEMM: C[m,n] = sum_k A[m,k] * B[n,k] + bias[n]
// M=32768, N=1024, K=1024. 128x128 tile, BK=8, 256 thr, 8x8 micro-tile,
// double-buffered smem (one __syncthreads per k-tile).
// ---------------------------------------------------------------------------
__global__ void __launch_bounds__(256, 2)
gemm_kernel(const float* __restrict__ A, const float* __restrict__ Bw,
            const float* __restrict__ bias, float* __restrict__ C) {
    __shared__ float As[2][8][128];
    __shared__ float Bs[2][8][128];

    const int tid = threadIdx.x;
    const int m0 = blockIdx.x * 128;
    const int n0 = blockIdx.y * 128;
    const int lr = tid >> 1;          // 0..127
    const int lc = (tid & 1) * 4;     // 0 or 4
    const int tx = tid & 15;
    const int ty = tid >> 4;

    const float* Ab = A  + (size_t)(m0 + lr) * DIM + lc;
    const float* Bb = Bw + (size_t)(n0 + lr) * DIM + lc;

    float acc[8][8];
#pragma unroll
    for (int i = 0; i < 8; i++)
#pragma unroll
        for (int j = 0; j < 8; j++) acc[i][j] = 0.0f;

    // Preload tile 0 into buffer 0.
    {
        float4 a4 = *(const float4*)Ab;
        float4 b4 = *(const float4*)Bb;
        As[0][lc + 0][lr] = a4.x; As[0][lc + 1][lr] = a4.y;
        As[0][lc + 2][lr] = a4.z; As[0][lc + 3][lr] = a4.w;
        Bs[0][lc + 0][lr] = b4.x; Bs[0][lc + 1][lr] = b4.y;
        Bs[0][lc + 2][lr] = b4.z; Bs[0][lc + 3][lr] = b4.w;
    }
    __syncthreads();

#pragma unroll 1
    for (int kt = 0; kt < 128; kt++) {
        const int cur = kt & 1;
        float4 na, nb;
        if (kt < 127) {
            na = *(const float4*)(Ab + (kt + 1) * 8);
            nb = *(const float4*)(Bb + (kt + 1) * 8);
        }

#pragma unroll
        for (int kk = 0; kk < 8; kk++) {
            float af[8], bf[8];
            *(float4*)&af[0] = *(const float4*)&As[cur][kk][ty * 8];
            *(float4*)&af[4] = *(const float4*)&As[cur][kk][ty * 8 + 4];
            *(float4*)&bf[0] = *(const float4*)&Bs[cur][kk][tx * 8];
            *(float4*)&bf[4] = *(const float4*)&Bs[cur][kk][tx * 8 + 4];
#pragma unroll
            for (int i = 0; i < 8; i++)
#pragma unroll
                for (int j = 0; j < 8; j++)
                    acc[i][j] = fmaf(af[i], bf[j], acc[i][j]);
        }

        if (kt < 127) {
            const int nxt = cur ^ 1;
            As[nxt][lc + 0][lr] = na.x; As[nxt][lc + 1][lr] = na.y;
            As[nxt][lc + 2][lr] = na.z; As[nxt][lc + 3][lr] = na.w;
            Bs[nxt][lc + 0][lr] = nb.x; Bs[nxt][lc + 1][lr] = nb.y;
            Bs[nxt][lc + 2][lr] = nb.z; Bs[nxt][lc + 3][lr] = nb.w;
        }
        __syncthreads();
    }

#pragma unroll
    for (int i = 0; i < 8; i++) {
        size_t row = (size_t)(m0 + ty * 8 + i) * DIM + n0 + tx * 8;
#pragma unroll
        for (int j = 0; j < 8; j++)
            C[row + j] = acc[i][j] + bias[n0 + tx * 8 + j];
    }
}

// ---------------------------------------------------------------------------
// Persistent recurrence. 128 CTAs x 256 threads; CTA owns 8 output columns.
// Thread (e_loc = tid&7, chunk = tid>>3) holds W_h[e, chunk*32..+31] in regs
// (bank-rotated). Per step: 4-group cp.async pipeline of h (4 batches/group)
// overlapped with the FMA on already-arrived groups.
// ---------------------------------------------------------------------------
__global__ void __launch_bounds__(256, 1)
rnn_kernel(const float* __restrict__ Wh, const float* __restrict__ la,
           float* __restrict__ outs, float* __restrict__ hbuf) {
    extern __shared__ float sm[];
    float* h_sh = sm;            // 16384 floats (64 KB)
    float* part = sm + 16384;    // 4096 floats  (16 KB)

    const int tid   = threadIdx.x;
    const int e_loc = tid & 7;
    const int chunk = tid >> 3;        // 0..31
    const int k0    = chunk * 32;
    const int e     = blockIdx.x * 8 + e_loc;
    const int rot   = chunk & 7;

    const float alpha = __expf(la[0]);

    float4 w4[8];
    int joff[8];
    {
        const float4* wp = reinterpret_cast<const float4*>(Wh + (size_t)e * DIM + k0);
#pragma unroll
        for (int jj = 0; jj < 8; jj++) {
            int j = (jj + rot) & 7;
            w4[jj]   = wp[j];
            joff[jj] = 4 * j;
        }
    }

    const int fb = tid >> 3;   // finalize: batch row (tid < 128)
    const int fe = tid & 7;    // finalize: local e column
    const int eg = blockIdx.x * 8 + fe;

    const uint32_t h_sh_base = (uint32_t)__cvta_generic_to_shared(h_sh);

    for (int t = 0; t < T_STEPS; t++) {
        const size_t obase = (size_t)t * STEP_ELEMS;

        // Prefetch wx early.
        float wx = 0.0f;
        if (tid < 128) wx = outs[obase + (size_t)fb * DIM + eg];

        // Issue all 4 h-groups as cp.async (L2 path), one commit per group.
        {
            const float4* src = reinterpret_cast<const float4*>(hbuf + obase);
#pragma unroll
            for (int g = 0; g < 4; g++) {
#pragma unroll
                for (int i = 0; i < 4; i++) {
                    int idx = g * 1024 + i * 256 + tid;     // float4 index
                    cp_async16(h_sh_base + (uint32_t)idx * 16u, src + idx);
                }
                cp_commit();
            }
        }

        float acc[16];
#pragma unroll
        for (int b = 0; b < 16; b++) acc[b] = 0.0f;

#define RNN_GROUP(G, WAITN)                                                     \
        do {                                                                    \
            CP_WAIT(WAITN);                                                     \
            __syncthreads();                                                    \
            _Pragma("unroll")                                                   \
            for (int jj = 0; jj < 8; jj++) {                                    \
                const float4 w = w4[jj];                                        \
                const int off = k0 + joff[jj];                                  \
                _Pragma("unroll")                                               \
                for (int bb = 0; bb < 4; bb++) {                                \
                    const int b = (G) * 4 + bb;                                 \
                    float4 h4 = *(const float4*)(h_sh + b * DIM + off);         \
                    float a = acc[b];                                           \
                    a = fmaf(h4.x, w.x, a);                                     \
                    a = fmaf(h4.y, w.y, a);                                     \
                    a = fmaf(h4.z, w.z, a);                                     \
                    a = fmaf(h4.w, w.w, a);                                     \
                    acc[b] = a;                                                 \
                }                                                               \
            }                                                                   \
        } while (0)

        RNN_GROUP(0, 3);
        RNN_GROUP(1, 2);
        RNN_GROUP(2, 1);
        RNN_GROUP(3, 0);
#undef RNN_GROUP

#pragma unroll
        for (int b = 0; b < 16; b++)
            part[(chunk * 16 + b) * 8 + e_loc] = acc[b];
        __syncthreads();

        float ot = 0.0f;
        if (tid < 128) {
            float s0 = 0.f, s1 = 0.f, s2 = 0.f, s3 = 0.f;
#pragma unroll
            for (int c = 0; c < 32; c += 4) {
                s0 += part[((c + 0) * 16 + fb) * 8 + fe];
                s1 += part[((c + 1) * 16 + fb) * 8 + fe];
                s2 += part[((c + 2) * 16 + fb) * 8 + fe];
                s3 += part[((c + 3) * 16 + fb) * 8 + fe];
            }
            float pre  = (s0 + s1) + (s2 + s3) + wx;
            float hold = h_sh[fb * DIM + eg];
            float hn   = hold + alpha * my_tanh(pre);
            ot         = hn * hn * my_sigmoid(hn);
            __stcg(&hbuf[(size_t)(t + 1) * STEP_ELEMS + (size_t)fb * DIM + eg], hn);
        }
        __syncthreads();   // all h-slice stores of this CTA are done

        // Arrive (release orders the stcg's published via the syncthreads).
        if (tid == 0) bar_arrive_release();

        // Overlap the outs store with other CTAs arriving / our poll.
        if (tid < 128) outs[obase + (size_t)fb * DIM + eg] = ot;

        if (tid == 0) {
            const unsigned tgt = (unsigned)(t + 1) * NCTA;
            while (bar_ld_acquire() < tgt) { }
        }
        __syncthreads();
    }
}

// ---------------------------------------------------------------------------
// kernel_launch
//   inputs: x[T,B,D], h0[B,D], W_x[D,D], W_h[D,D], b[D], log_alpha[1]
//   output: [ outs (T*B*D) | h ((T+1)*B*D) ] float32
//   outs doubles as Wx_all scratch: gemm writes Wx there, rnn reads wx[t,b,e]
//   and overwrites the same element with out[t,b,e].
// ---------------------------------------------------------------------------
extern "C" void kernel_launch(void* const* d_in, const int* in_sizes, int n_in,
                              void* d_out, int out_size) {
    const float* x    = (const float*)d_in[0];
    const float* h0   = (const float*)d_in[1];
    const float* Wx   = (const float*)d_in[2];
    const float* Wh   = (const float*)d_in[3];
    const float* bias = (const float*)d_in[4];
    const float* la   = (const float*)d_in[5];

    float* outs = (float*)d_out;
    float* hbuf = outs + OUTS_ELEMS;

    cudaFuncSetAttribute(rnn_kernel, cudaFuncAttributeMaxDynamicSharedMemorySize,
                         (16384 + 4096) * sizeof(float));

    init_kernel<<<32, 512>>>(h0, hbuf);

    dim3 gg(32768 / 128, DIM / 128);
    gemm_kernel<<<gg, 256>>>(x, Wx, bias, outs);

    rnn_kernel<<<NCTA, 256, (16384 + 4096) * sizeof(float)>>>(Wh, la, outs, hbuf);
}